// round 15
// baseline (speedup 1.0000x reference)
#include <cuda_runtime.h>
#include <cuda_bf16.h>
#include <math.h>
#include <stdint.h>

#define NN    4096
#define FIN   512
#define FH    128
#define NH    4
#define FOUT  64
#define FCAT  512
#define JS1   4
#define JS2   8

// ---------------- scratch ----------------------------------------------------
__device__ unsigned g_bitsT[NN * NN / 32];     // bitsT[(j>>5)*NN + i]
__device__ float  g_hcat[NN * FCAT];
__device__ float  g_h2  [NN * FOUT];
__device__ uint32_t g_Hp1[(NN / 2) * FCAT];    // bf16x2 k-packed hcat
__device__ uint32_t g_Hp2[(NN / 2) * FOUT];    // bf16x2 k-packed h2
__device__ float  g_s1  [NH * NN];
__device__ float  g_s1o [NN];
__device__ float2 g_Bp1 [NH * NN];             // (exp(t2), exp(0.2*t2))
__device__ float2 g_Bp2 [NN];
__device__ unsigned g_Tenc[NH + 1];
__device__ float  g_p1  [JS1 * NN * FCAT];
__device__ float  g_sp1 [JS1 * NH * NN];
__device__ float  g_p2  [JS2 * NN * FOUT];
__device__ float  g_sp2 [JS2 * NN];

// ---------------- helpers ----------------------------------------------------
__device__ __forceinline__ uint32_t f2tf32(float x) {
    uint32_t r;
    asm("cvt.rna.tf32.f32 %0, %1;" : "=r"(r) : "f"(x));
    return r;
}
__device__ __forceinline__ float tf32r(float x) { return __uint_as_float(f2tf32(x)); }
__device__ __forceinline__ void mma8(float* c, const uint32_t* a, const uint32_t* b) {
    asm volatile(
        "mma.sync.aligned.m16n8k8.row.col.f32.tf32.tf32.f32 "
        "{%0,%1,%2,%3},{%4,%5,%6,%7},{%8,%9},{%0,%1,%2,%3};"
        : "+f"(c[0]), "+f"(c[1]), "+f"(c[2]), "+f"(c[3])
        : "r"(a[0]), "r"(a[1]), "r"(a[2]), "r"(a[3]), "r"(b[0]), "r"(b[1]));
}
__device__ __forceinline__ void mma16(float* c, const uint32_t* a, const uint32_t* b) {
    asm volatile(
        "mma.sync.aligned.m16n8k16.row.col.f32.bf16.bf16.f32 "
        "{%0,%1,%2,%3},{%4,%5,%6,%7},{%8,%9},{%0,%1,%2,%3};"
        : "+f"(c[0]), "+f"(c[1]), "+f"(c[2]), "+f"(c[3])
        : "r"(a[0]), "r"(a[1]), "r"(a[2]), "r"(a[3]), "r"(b[0]), "r"(b[1]));
}
__device__ __forceinline__ unsigned fenc(float f) {
    unsigned u = __float_as_uint(f);
    return u ^ ((u >> 31) ? 0xFFFFFFFFu : 0x80000000u);
}
__device__ __forceinline__ float fdec(unsigned u) {
    return __uint_as_float(u ^ ((u & 0x80000000u) ? 0x80000000u : 0xFFFFFFFFu));
}
__device__ __forceinline__ void cpa16(uint32_t dst, const void* src) {
    asm volatile("cp.async.ca.shared.global [%0], [%1], 16;" :: "r"(dst), "l"(src));
}
#define CP_COMMIT() asm volatile("cp.async.commit_group;")
#define CP_WAIT0()  asm volatile("cp.async.wait_group 0;")
__device__ __forceinline__ uint32_t packbf(float lo, float hi) {
    __nv_bfloat162 p = __floats2bfloat162_rn(lo, hi);
    return *reinterpret_cast<uint32_t*>(&p);
}

// ---------------- pack adjacency to transposed bits (int4 + or-reduce) -------
__global__ __launch_bounds__(256) void pack_k(const int* __restrict__ adj,
                                              unsigned* __restrict__ bitsT,
                                              unsigned* __restrict__ Tenc)
{
    int i = blockIdx.x;
    int t = threadIdx.x, lane = t & 31, w = t >> 5;
    if (i == 0 && t < NH + 1) Tenc[t] = 0u;
    for (int base = w * 128; base < NN; base += 8 * 128) {
        int4 a = *(const int4*)(adj + (size_t)i * NN + base + lane * 4);
        unsigned nib = (unsigned)(a.x > 0) | ((unsigned)(a.y > 0) << 1)
                     | ((unsigned)(a.z > 0) << 2) | ((unsigned)(a.w > 0) << 3);
        unsigned v = nib << (4 * (lane & 7));
        v |= __shfl_xor_sync(0xffffffffu, v, 1);
        v |= __shfl_xor_sync(0xffffffffu, v, 2);
        v |= __shfl_xor_sync(0xffffffffu, v, 4);
        if ((lane & 7) == 0)
            bitsT[(size_t)((base >> 5) + (lane >> 3)) * NN + i] = v;
    }
}

// ---------------- stage1 feature GEMM (tf32 mma, reg double buffer) ----------
__global__ __launch_bounds__(128) void gemm1_k(
    const float* __restrict__ A, const float* __restrict__ W,
    const float* __restrict__ bias, float* __restrict__ C)
{
    __shared__ float As[2][16][72];
    __shared__ float Bs[2][16][136];
    const int head = blockIdx.y;
    const int rowBase = blockIdx.x * 64;
    const int t = threadIdx.x;
    const int lane = t & 31, wid = t >> 5;
    const int gid = lane >> 2, tig = lane & 3;
    const int mw = wid >> 1, nw = wid & 1;
    const float* Wh = W + (size_t)head * FIN * FH;
    const int arow = t >> 1, akc = (t & 1) << 3;

    float acc[2][8][4] = {};
    float ar[8], br[16];

    auto LDG = [&](int k0) {
        float4 a0 = *(const float4*)(A + (size_t)(rowBase + arow) * FIN + k0 + akc);
        float4 a1 = *(const float4*)(A + (size_t)(rowBase + arow) * FIN + k0 + akc + 4);
        ar[0] = a0.x; ar[1] = a0.y; ar[2] = a0.z; ar[3] = a0.w;
        ar[4] = a1.x; ar[5] = a1.y; ar[6] = a1.z; ar[7] = a1.w;
        #pragma unroll
        for (int v = 0; v < 4; v++) {
            int idx = t + v * 128;
            int kr = idx >> 5, cc = (idx & 31) << 2;
            float4 b = *(const float4*)(Wh + (size_t)(k0 + kr) * FH + cc);
            br[4 * v + 0] = b.x; br[4 * v + 1] = b.y;
            br[4 * v + 2] = b.z; br[4 * v + 3] = b.w;
        }
    };
    auto STS = [&](int bb) {
        #pragma unroll
        for (int q = 0; q < 8; q++) As[bb][akc + q][arow] = tf32r(ar[q]);
        #pragma unroll
        for (int v = 0; v < 4; v++) {
            int idx = t + v * 128;
            int kr = idx >> 5, cc = (idx & 31) << 2;
            float4 o = {tf32r(br[4 * v]), tf32r(br[4 * v + 1]),
                        tf32r(br[4 * v + 2]), tf32r(br[4 * v + 3])};
            *(float4*)&Bs[bb][kr][cc] = o;
        }
    };

    LDG(0); STS(0);
    __syncthreads();
    const int NIT = FIN / 16;
    for (int n = 0; n < NIT; n++) {
        const int b = n & 1;
        if (n + 1 < NIT) LDG((n + 1) * 16);
        #pragma unroll
        for (int kc = 0; kc < 2; kc++) {
            int kk = kc * 8;
            uint32_t af[2][4];
            #pragma unroll
            for (int mt = 0; mt < 2; mt++) {
                int rb = mw * 32 + mt * 16;
                af[mt][0] = __float_as_uint(As[b][kk + tig][rb + gid]);
                af[mt][1] = __float_as_uint(As[b][kk + tig][rb + gid + 8]);
                af[mt][2] = __float_as_uint(As[b][kk + tig + 4][rb + gid]);
                af[mt][3] = __float_as_uint(As[b][kk + tig + 4][rb + gid + 8]);
            }
            #pragma unroll
            for (int nt = 0; nt < 8; nt++) {
                int cb = nw * 64 + nt * 8;
                uint32_t bf[2];
                bf[0] = __float_as_uint(Bs[b][kk + tig][cb + gid]);
                bf[1] = __float_as_uint(Bs[b][kk + tig + 4][cb + gid]);
                mma8(acc[0][nt], af[0], bf);
                mma8(acc[1][nt], af[1], bf);
            }
        }
        if (n + 1 < NIT) STS(b ^ 1);
        __syncthreads();
    }
    #pragma unroll
    for (int mt = 0; mt < 2; mt++) {
        int r0 = rowBase + mw * 32 + mt * 16 + gid;
        #pragma unroll
        for (int nt = 0; nt < 8; nt++) {
            int c0 = nw * 64 + nt * 8 + tig * 2;
            float b0 = bias[head * FH + c0], b1 = bias[head * FH + c0 + 1];
            float2 lo = {acc[mt][nt][0] + b0, acc[mt][nt][1] + b1};
            float2 hi = {acc[mt][nt][2] + b0, acc[mt][nt][3] + b1};
            *(float2*)(C + (size_t)r0 * FCAT + head * FH + c0) = lo;
            *(float2*)(C + (size_t)(r0 + 8) * FCAT + head * FH + c0) = hi;
        }
    }
}

// ---------------- fused logits + global max + B pairs + bf16 pack ------------
template <int COLS, int NHH>
__global__ __launch_bounds__(256) void sdotpack_k(
    const float* __restrict__ Hmat,
    const float* __restrict__ a1, const float* __restrict__ a2,
    const float* __restrict__ ab,
    float* __restrict__ s1, float2* __restrict__ Bp,
    unsigned* __restrict__ Tenc, uint32_t* __restrict__ Hp)
{
    const int F = COLS / NHH;
    __shared__ float rows[8][COLS];
    __shared__ float sa1[COLS], sa2[COLS];
    const int i0 = blockIdx.x * 8;
    const int t = threadIdx.x;
    for (int c = t; c < COLS; c += 256) { sa1[c] = a1[c]; sa2[c] = a2[c]; }
    for (int idx = t * 4; idx < 8 * COLS; idx += 1024) {
        int r = idx / COLS, c = idx % COLS;
        *(float4*)&rows[r][c] = *(const float4*)(Hmat + (size_t)(i0 + r) * COLS + c);
    }
    __syncthreads();

    const int w = t >> 5, lane = t & 31;
    float d1h[NHH], d2h[NHH];
    #pragma unroll
    for (int h = 0; h < NHH; h++) { d1h[h] = 0.f; d2h[h] = 0.f; }
    #pragma unroll
    for (int q = 0; q < COLS / 32; q++) {
        int c = lane + 32 * q;
        int h = q / (F / 32);
        float v = rows[w][c];
        d1h[h] = fmaf(v, sa1[c], d1h[h]);
        d2h[h] = fmaf(v, sa2[c], d2h[h]);
    }
    #pragma unroll
    for (int h = 0; h < NHH; h++) {
        #pragma unroll
        for (int off = 16; off; off >>= 1) {
            d1h[h] += __shfl_xor_sync(0xffffffffu, d1h[h], off);
            d2h[h] += __shfl_xor_sync(0xffffffffu, d2h[h], off);
        }
    }
    if (lane == 0) {
        int i = i0 + w;
        #pragma unroll
        for (int h = 0; h < NHH; h++) {
            s1[h * NN + i] = d1h[h];
            float tv = d2h[h] + ab[h];
            atomicMax(&Tenc[h], fenc(tv));
            Bp[h * NN + i] = make_float2(__expf(tv), __expf(0.2f * tv));
        }
    }
    for (int idx = t; idx < 4 * COLS; idx += 256) {
        int p = idx / COLS, c = idx % COLS;
        Hp[(size_t)(i0 / 2 + p) * COLS + c] = packbf(rows[2 * p][c], rows[2 * p + 1][c]);
    }
}

// ---------------- stage1 aggregation: bf16 mma, 256 thr, BK=32 ---------------
// BM=64, BN=128, BK=32. grid (NN/64, NH, JS1)
__global__ __launch_bounds__(256) void agg1_k(
    const unsigned* __restrict__ bitsT,
    const float* __restrict__ s1a,
    const float2* __restrict__ Bp,
    const unsigned* __restrict__ Tg,
    const uint32_t* __restrict__ Hp,
    float* __restrict__ part, float* __restrict__ psums)
{
    const int SL = NN / JS1;                       // 1024
    __shared__ __align__(16) uint32_t Ps2[2][16][72];
    __shared__ __align__(16) uint32_t Hs2[2][16][136];
    __shared__ __align__(16) float2 sBp[SL];       // 8 KB
    __shared__ unsigned sbits[64][33];             // 8.4 KB
    __shared__ float spart[4][64];

    const int head = blockIdx.y;
    const int i0 = blockIdx.x * 64;
    const int kb = blockIdx.z;
    const int t = threadIdx.x;
    const int lane = t & 31, wid = t >> 5;
    const int gid = lane >> 2, tig = lane & 3;
    const int mw = wid >> 2, nwq = wid & 3;
    const int r = t & 63, quarter = t >> 6;
    const int js = kb * SL;

    float T = fdec(Tg[head]);
    float s1v = s1a[head * NN + i0 + r];
    float zz = s1v + T;
    float cc = fmaxf(zz, 0.2f * zz);
    float Av  = __expf(s1v - cc);
    float A2v = __expf(0.2f * s1v - cc);

    {
        const float2* BpH = Bp + head * NN + js;
        for (int q = t; q < SL; q += 256) sBp[q] = BpH[q];
        #pragma unroll
        for (int k = 0; k < SL / 32; k += 4) {
            int w = quarter + k;
            sbits[r][w] = bitsT[(size_t)(js / 32 + w) * NN + i0 + r];
        }
    }
    uint32_t hs0 = (uint32_t)__cvta_generic_to_shared(&Hs2[0][0][0]);
    __syncthreads();

    float acc[2][4][4] = {};
    float psum = 0.f;
    const int NCH = SL / 32;                       // 32 chunks

    auto fill = [&](int n, int b) {
        int jl = n * 32;
        unsigned w = sbits[r][n];
        unsigned hw = w >> (quarter * 8);
        const float4* bv = (const float4*)(&sBp[jl + quarter * 8]);
        #pragma unroll
        for (int q = 0; q < 4; q++) {
            float4 f = bv[q];
            float p0 = fmaxf(Av * f.x, A2v * f.y);
            float p1 = fmaxf(Av * f.z, A2v * f.w);
            int m0 = ((int)(hw << (31 - 2 * q))) >> 31;
            int m1 = ((int)(hw << (30 - 2 * q))) >> 31;
            p0 = __uint_as_float(__float_as_uint(p0) & (unsigned)m0);
            p1 = __uint_as_float(__float_as_uint(p1) & (unsigned)m1);
            __nv_bfloat162 pb = __floats2bfloat162_rn(p0, p1);
            psum += __low2float(pb) + __high2float(pb);
            Ps2[b][quarter * 4 + q][r] = *reinterpret_cast<uint32_t*>(&pb);
        }
        const uint32_t* hsrc = Hp + (size_t)((js + jl) >> 1) * FCAT + head * FH;
        uint32_t hb = hs0 + (uint32_t)b * (16 * 136 * 4);
        #pragma unroll
        for (int v = 0; v < 2; v++) {
            int idx = t + v * 256;
            int kr = idx >> 5, c16 = idx & 31;
            cpa16(hb + kr * (136 * 4) + c16 * 16,
                  hsrc + (size_t)kr * FCAT + c16 * 4);
        }
    };

    fill(0, 0);
    CP_COMMIT();
    CP_WAIT0();
    __syncthreads();
    for (int n = 0; n < NCH; n++) {
        const int b = n & 1;
        if (n + 1 < NCH) { fill(n + 1, b ^ 1); CP_COMMIT(); }
        #pragma unroll
        for (int ks = 0; ks < 2; ks++) {
            int kk = ks * 8;
            uint32_t af[2][4];
            #pragma unroll
            for (int mt = 0; mt < 2; mt++) {
                int rb = mw * 32 + mt * 16;
                af[mt][0] = Ps2[b][kk + tig][rb + gid];
                af[mt][1] = Ps2[b][kk + tig][rb + gid + 8];
                af[mt][2] = Ps2[b][kk + tig + 4][rb + gid];
                af[mt][3] = Ps2[b][kk + tig + 4][rb + gid + 8];
            }
            #pragma unroll
            for (int nt = 0; nt < 4; nt++) {
                int cb = nwq * 32 + nt * 8;
                uint32_t bf[2];
                bf[0] = Hs2[b][kk + tig][cb + gid];
                bf[1] = Hs2[b][kk + tig + 4][cb + gid];
                mma16(acc[0][nt], af[0], bf);
                mma16(acc[1][nt], af[1], bf);
            }
        }
        CP_WAIT0();
        __syncthreads();
    }
    spart[quarter][r] = psum;
    __syncthreads();
    if (t < 64)
        psums[((size_t)kb * NH + head) * NN + i0 + t] =
            spart[0][t] + spart[1][t] + spart[2][t] + spart[3][t];
    float* pb = part + (size_t)kb * NN * FCAT;
    #pragma unroll
    for (int mt = 0; mt < 2; mt++) {
        int r0 = i0 + mw * 32 + mt * 16 + gid;
        #pragma unroll
        for (int nt = 0; nt < 4; nt++) {
            int c0 = head * FH + nwq * 32 + nt * 8 + tig * 2;
            float2 lo = {acc[mt][nt][0], acc[mt][nt][1]};
            float2 hi = {acc[mt][nt][2], acc[mt][nt][3]};
            *(float2*)(pb + (size_t)r0 * FCAT + c0) = lo;
            *(float2*)(pb + (size_t)(r0 + 8) * FCAT + c0) = hi;
        }
    }
}

// ---------------- stage2 feature GEMM, FUSED normalize+elu A-load ------------
// h2 = (elu(combine(p1)/rowsum)) @ W_o + b_o.  BM=64, BN=64, 128 thr. grid NN/64.
__global__ __launch_bounds__(128) void gemm2f_k(
    const float* __restrict__ p1, const float* __restrict__ sp1,
    const float* __restrict__ W, const float* __restrict__ bias,
    float* __restrict__ C)
{
    __shared__ float As[2][16][72];
    __shared__ float Bs[2][16][72];
    const int rowBase = blockIdx.x * 64;
    const int t = threadIdx.x;
    const int lane = t & 31, wid = t >> 5;
    const int gid = lane >> 2, tig = lane & 3;
    const int mw = wid >> 1, nw = wid & 1;
    const int arow = t >> 1, akc = (t & 1) << 3;
    const int myrow = rowBase + arow;

    // per-row, per-head inverse softmax sums
    float iv0, iv1, iv2, iv3;
    {
        float s0 = 0.f, s1s = 0.f, s2s = 0.f, s3s = 0.f;
        #pragma unroll
        for (int k = 0; k < JS1; k++) {
            s0  += sp1[((size_t)k * NH + 0) * NN + myrow];
            s1s += sp1[((size_t)k * NH + 1) * NN + myrow];
            s2s += sp1[((size_t)k * NH + 2) * NN + myrow];
            s3s += sp1[((size_t)k * NH + 3) * NN + myrow];
        }
        iv0 = 1.f / s0; iv1 = 1.f / s1s; iv2 = 1.f / s2s; iv3 = 1.f / s3s;
    }

    float acc[2][4][4] = {};
    float ar[8], br[8];

    auto LDG = [&](int k0) {
        int head = k0 >> 7;
        float inv = head < 2 ? (head == 0 ? iv0 : iv1) : (head == 2 ? iv2 : iv3);
        const float* pbase = p1 + (size_t)myrow * FCAT + k0 + akc;
        float4 a0 = {0.f, 0.f, 0.f, 0.f}, a1 = {0.f, 0.f, 0.f, 0.f};
        #pragma unroll
        for (int k = 0; k < JS1; k++) {
            float4 q0 = *(const float4*)(pbase + (size_t)k * NN * FCAT);
            float4 q1 = *(const float4*)(pbase + (size_t)k * NN * FCAT + 4);
            a0.x += q0.x; a0.y += q0.y; a0.z += q0.z; a0.w += q0.w;
            a1.x += q1.x; a1.y += q1.y; a1.z += q1.z; a1.w += q1.w;
        }
        float v;
        v = a0.x * inv; ar[0] = v > 0.f ? v : expm1f(v);
        v = a0.y * inv; ar[1] = v > 0.f ? v : expm1f(v);
        v = a0.z * inv; ar[2] = v > 0.f ? v : expm1f(v);
        v = a0.w * inv; ar[3] = v > 0.f ? v : expm1f(v);
        v = a1.x * inv; ar[4] = v > 0.f ? v : expm1f(v);
        v = a1.y * inv; ar[5] = v > 0.f ? v : expm1f(v);
        v = a1.z * inv; ar[6] = v > 0.f ? v : expm1f(v);
        v = a1.w * inv; ar[7] = v > 0.f ? v : expm1f(v);
        #pragma unroll
        for (int v2 = 0; v2 < 2; v2++) {
            int idx = t + v2 * 128;
            int kr = idx >> 4, cc = (idx & 15) << 2;
            float4 b = *(const float4*)(W + (size_t)(k0 + kr) * FOUT + cc);
            br[4 * v2 + 0] = b.x; br[4 * v2 + 1] = b.y;
            br[4 * v2 + 2] = b.z; br[4 * v2 + 3] = b.w;
        }
    };
    auto STS = [&](int bb) {
        #pragma unroll
        for (int q = 0; q < 8; q++) As[bb][akc + q][arow] = tf32r(ar[q]);
        #pragma unroll
        for (int v = 0; v < 2; v++) {
            int idx = t + v * 128;
            int kr = idx >> 4, cc = (idx & 15) << 2;
            float4 o = {tf32r(br[4 * v]), tf32r(br[4 * v + 1]),
                        tf32r(br[4 * v + 2]), tf32r(br[4 * v + 3])};
            *(float4*)&Bs[bb][kr][cc] = o;
        }
    };

    LDG(0); STS(0);
    __syncthreads();
    const int NIT = FCAT / 16;
    for (int n = 0; n < NIT; n++) {
        const int b = n & 1;
        if (n + 1 < NIT) LDG((n + 1) * 16);
        #pragma unroll
        for (int kc = 0; kc < 2; kc++) {
            int kk = kc * 8;
            uint32_t af[2][4];
            #pragma unroll
            for (int mt = 0; mt < 2; mt++) {
                int rb = mw * 32 + mt * 16;
                af[mt][0] = __float_as_uint(As[b][kk + tig][rb + gid]);
                af[mt][1] = __float_as_uint(As[b][kk + tig][rb + gid + 8]);
                af[mt][2] = __float_as_uint(As[b][kk + tig + 4][rb + gid]);
                af[mt][3] = __float_as_uint(As[b][kk + tig + 4][rb + gid + 8]);
            }
            #pragma unroll
            for (int nt = 0; nt < 4; nt++) {
                int cb = nw * 32 + nt * 8;
                uint32_t bf[2];
                bf[0] = __float_as_uint(Bs[b][kk + tig][cb + gid]);
                bf[1] = __float_as_uint(Bs[b][kk + tig + 4][cb + gid]);
                mma8(acc[0][nt], af[0], bf);
                mma8(acc[1][nt], af[1], bf);
            }
        }
        if (n + 1 < NIT) STS(b ^ 1);
        __syncthreads();
    }
    #pragma unroll
    for (int mt = 0; mt < 2; mt++) {
        int r0 = rowBase + mw * 32 + mt * 16 + gid;
        #pragma unroll
        for (int nt = 0; nt < 4; nt++) {
            int c0 = nw * 32 + nt * 8 + tig * 2;
            float b0 = bias[c0], b1 = bias[c0 + 1];
            float2 lo = {acc[mt][nt][0] + b0, acc[mt][nt][1] + b1};
            float2 hi = {acc[mt][nt][2] + b0, acc[mt][nt][3] + b1};
            *(float2*)(C + (size_t)r0 * FOUT + c0) = lo;
            *(float2*)(C + (size_t)(r0 + 8) * FOUT + c0) = hi;
        }
    }
}

// ---------------- stage2 aggregation split-K (bf16 mma, 256 thr, BK=32) -----
// BM=64, BN=64, BK=32. grid (NN/64, JS2)
__global__ __launch_bounds__(256) void agg2_k(
    const unsigned* __restrict__ bitsT,
    const float* __restrict__ s1a,
    const float2* __restrict__ Bp,
    const unsigned* __restrict__ Tg,
    const uint32_t* __restrict__ Hp,
    float* __restrict__ part, float* __restrict__ psums)
{
    const int SL = NN / JS2;                       // 512
    __shared__ __align__(16) uint32_t Ps2[2][16][72];
    __shared__ __align__(16) uint32_t Hs2[2][16][72];
    __shared__ __align__(16) float2 sBp[SL];
    __shared__ unsigned sbits[64][17];
    __shared__ float spart[4][64];

    const int i0 = blockIdx.x * 64;
    const int kb = blockIdx.y;
    const int t = threadIdx.x;
    const int lane = t & 31, wid = t >> 5;
    const int gid = lane >> 2, tig = lane & 3;
    const int mw = wid >> 2, nwq = wid & 3;
    const int r = t & 63, quarter = t >> 6;
    const int js = kb * SL;

    float T = fdec(Tg[0]);
    float s1v = s1a[i0 + r];
    float zz = s1v + T;
    float cc = fmaxf(zz, 0.2f * zz);
    float Av  = __expf(s1v - cc);
    float A2v = __expf(0.2f * s1v - cc);

    {
        const float2* BpS = Bp + js;
        for (int q = t; q < SL; q += 256) sBp[q] = BpS[q];
        #pragma unroll
        for (int k = 0; k < SL / 32; k += 4) {
            int w = quarter + k;
            sbits[r][w] = bitsT[(size_t)(js / 32 + w) * NN + i0 + r];
        }
    }
    uint32_t hs0 = (uint32_t)__cvta_generic_to_shared(&Hs2[0][0][0]);
    __syncthreads();

    float acc[2][2][4] = {};
    float psum = 0.f;
    const int NCH = SL / 32;                       // 16 chunks

    auto fill = [&](int n, int b) {
        int jl = n * 32;
        unsigned w = sbits[r][n];
        unsigned hw = w >> (quarter * 8);
        const float4* bv = (const float4*)(&sBp[jl + quarter * 8]);
        #pragma unroll
        for (int q = 0; q < 4; q++) {
            float4 f = bv[q];
            float p0 = fmaxf(Av * f.x, A2v * f.y);
            float p1 = fmaxf(Av * f.z, A2v * f.w);
            int m0 = ((int)(hw << (31 - 2 * q))) >> 31;
            int m1 = ((int)(hw << (30 - 2 * q))) >> 31;
            p0 = __uint_as_float(__float_as_uint(p0) & (unsigned)m0);
            p1 = __uint_as_float(__float_as_uint(p1) & (unsigned)m1);
            __nv_bfloat162 pb = __floats2bfloat162_rn(p0, p1);
            psum += __low2float(pb) + __high2float(pb);
            Ps2[b][quarter * 4 + q][r] = *reinterpret_cast<uint32_t*>(&pb);
        }
        const uint32_t* hsrc = Hp + (size_t)((js + jl) >> 1) * FOUT;
        uint32_t hb = hs0 + (uint32_t)b * (16 * 72 * 4);
        {
            int kr = t >> 4, c16 = t & 15;
            cpa16(hb + kr * (72 * 4) + c16 * 16,
                  hsrc + (size_t)kr * FOUT + c16 * 4);
        }
    };

    fill(0, 0);
    CP_COMMIT();
    CP_WAIT0();
    __syncthreads();
    for (int n = 0; n < NCH; n++) {
        const int b = n & 1;
        if (n + 1 < NCH) { fill(n + 1, b ^ 1); CP_COMMIT(); }
        #pragma unroll
        for (int ks = 0; ks < 2; ks++) {
            int kk = ks * 8;
            uint32_t af[2][4];
            #pragma unroll
            for (int mt = 0; mt < 2; mt++) {
                int rb = mw * 32 + mt * 16;
                af[mt][0] = Ps2[b][kk + tig][rb + gid];
                af[mt][1] = Ps2[b][kk + tig][rb + gid + 8];
                af[mt][2] = Ps2[b][kk + tig + 4][rb + gid];
                af[mt][3] = Ps2[b][kk + tig + 4][rb + gid + 8];
            }
            #pragma unroll
            for (int nt = 0; nt < 2; nt++) {
                int cb = nwq * 16 + nt * 8;
                uint32_t bf[2];
                bf[0] = Hs2[b][kk + tig][cb + gid];
                bf[1] = Hs2[b][kk + tig + 4][cb + gid];
                mma16(acc[0][nt], af[0], bf);
                mma16(acc[1][nt], af[1], bf);
            }
        }
        CP_WAIT0();
        __syncthreads();
    }
    spart[quarter][r] = psum;
    __syncthreads();
    if (t < 64)
        psums[(size_t)kb * NN + i0 + t] =
            spart[0][t] + spart[1][t] + spart[2][t] + spart[3][t];
    float* pb = part + (size_t)kb * NN * FOUT;
    #pragma unroll
    for (int mt = 0; mt < 2; mt++) {
        int r0 = i0 + mw * 32 + mt * 16 + gid;
        #pragma unroll
        for (int nt = 0; nt < 2; nt++) {
            int c0 = nwq * 16 + nt * 8 + tig * 2;
            float2 lo = {acc[mt][nt][0], acc[mt][nt][1]};
            float2 hi = {acc[mt][nt][2], acc[mt][nt][3]};
            *(float2*)(pb + (size_t)r0 * FOUT + c0) = lo;
            *(float2*)(pb + (size_t)(r0 + 8) * FOUT + c0) = hi;
        }
    }
}

// ---------------- combine partials + normalize + elu + log_softmax ----------
__global__ void combine_k(const float* __restrict__ part,
                          const float* __restrict__ psums,
                          float* __restrict__ out)
{
    int i = blockIdx.x, c = threadIdx.x;  // 64 threads
    float v = 0.f, s = 0.f;
    #pragma unroll
    for (int k = 0; k < JS2; k++) {
        v += part[(size_t)k * NN * FOUT + (size_t)i * FOUT + c];
        s += psums[(size_t)k * NN + i];
    }
    v /= s;
    float e = v > 0.f ? v : expm1f(v);
    __shared__ float sh[4];
    float m = e;
    #pragma unroll
    for (int off = 16; off; off >>= 1)
        m = fmaxf(m, __shfl_xor_sync(0xffffffffu, m, off));
    if ((c & 31) == 0) sh[c >> 5] = m;
    __syncthreads();
    m = fmaxf(sh[0], sh[1]);
    float se = expf(e - m);
    #pragma unroll
    for (int off = 16; off; off >>= 1)
        se += __shfl_xor_sync(0xffffffffu, se, off);
    if ((c & 31) == 0) sh[2 + (c >> 5)] = se;
    __syncthreads();
    se = sh[2] + sh[3];
    out[(size_t)i * FOUT + c] = e - (m + logf(se));
}

// ---------------- launch -----------------------------------------------------
extern "C" void kernel_launch(void* const* d_in, const int* in_sizes, int n_in,
                              void* d_out, int out_size)
{
    const float* X    = (const float*)d_in[0];
    const int*   adj  = (const int*)  d_in[1];
    const float* W_h  = (const float*)d_in[2];
    const float* b_h  = (const float*)d_in[3];
    const float* a1_h = (const float*)d_in[4];
    const float* a2_h = (const float*)d_in[5];
    const float* ab_h = (const float*)d_in[6];
    const float* W_o  = (const float*)d_in[7];
    const float* b_o  = (const float*)d_in[8];
    const float* a1_o = (const float*)d_in[9];
    const float* a2_o = (const float*)d_in[10];
    const float* ab_o = (const float*)d_in[11];
    float* out = (float*)d_out;

    unsigned *bitsT, *Tenc;
    uint32_t *Hp1, *Hp2;
    float *hcat, *h2, *s1, *s1o, *p1, *sp1, *p2, *sp2;
    float2 *Bp1, *Bp2;
    cudaGetSymbolAddress((void**)&bitsT, g_bitsT);
    cudaGetSymbolAddress((void**)&Tenc,  g_Tenc);
    cudaGetSymbolAddress((void**)&hcat,  g_hcat);
    cudaGetSymbolAddress((void**)&h2,    g_h2);
    cudaGetSymbolAddress((void**)&Hp1,   g_Hp1);
    cudaGetSymbolAddress((void**)&Hp2,   g_Hp2);
    cudaGetSymbolAddress((void**)&s1,    g_s1);
    cudaGetSymbolAddress((void**)&s1o,   g_s1o);
    cudaGetSymbolAddress((void**)&Bp1,   g_Bp1);
    cudaGetSymbolAddress((void**)&Bp2,   g_Bp2);
    cudaGetSymbolAddress((void**)&p1,    g_p1);
    cudaGetSymbolAddress((void**)&sp1,   g_sp1);
    cudaGetSymbolAddress((void**)&p2,    g_p2);
    cudaGetSymbolAddress((void**)&sp2,   g_sp2);

    pack_k<<<NN, 256>>>(adj, bitsT, Tenc);

    {   dim3 grid(NN / 64, NH);
        gemm1_k<<<grid, 128>>>(X, W_h, b_h, hcat); }

    sdotpack_k<FCAT, NH><<<NN / 8, 256>>>(hcat, a1_h, a2_h, ab_h,
                                          s1, Bp1, Tenc, Hp1);

    {   dim3 grid(NN / 64, NH, JS1);
        agg1_k<<<grid, 256>>>(bitsT, s1, Bp1, Tenc, Hp1, p1, sp1); }

    gemm2f_k<<<NN / 64, 128>>>(p1, sp1, W_o, b_o, h2);

    sdotpack_k<FOUT, 1><<<NN / 8, 256>>>(h2, a1_o, a2_o, ab_o,
                                         s1o, Bp2, Tenc + NH, Hp2);

    {   dim3 grid(NN / 64, JS2);
        agg2_k<<<grid, 256>>>(bitsT, s1o, Bp2, Tenc + NH, Hp2, p2, sp2); }

    combine_k<<<NN, 64>>>(p2, sp2, out);
}

// round 16
// speedup vs baseline: 1.0653x; 1.0653x over previous
#include <cuda_runtime.h>
#include <cuda_bf16.h>
#include <math.h>
#include <stdint.h>

#define NN    4096
#define FIN   512
#define FH    128
#define NH    4
#define FOUT  64
#define FCAT  512
#define JS1   4
#define JS2   8

// ---------------- scratch ----------------------------------------------------
__device__ unsigned g_bitsT[NN * NN / 32];     // bitsT[(j>>5)*NN + i]
__device__ float  g_hcat[NN * FCAT];
__device__ float  g_x2  [NN * FCAT];
__device__ float  g_h2  [NN * FOUT];
__device__ uint32_t g_Hp1[(NN / 2) * FCAT];    // bf16x2 k-packed hcat
__device__ uint32_t g_Hp2[(NN / 2) * FOUT];    // bf16x2 k-packed h2
__device__ float  g_s1  [NH * NN];
__device__ float  g_s1o [NN];
__device__ float2 g_Bp1 [NH * NN];             // (exp(t2), exp(0.2*t2))
__device__ float2 g_Bp2 [NN];
__device__ unsigned g_Tenc[NH + 1];
__device__ float  g_p1  [JS1 * NN * FCAT];
__device__ float  g_sp1 [JS1 * NH * NN];
__device__ float  g_p2  [JS2 * NN * FOUT];
__device__ float  g_sp2 [JS2 * NN];

// ---------------- helpers ----------------------------------------------------
__device__ __forceinline__ uint32_t f2tf32(float x) {
    uint32_t r;
    asm("cvt.rna.tf32.f32 %0, %1;" : "=r"(r) : "f"(x));
    return r;
}
__device__ __forceinline__ float tf32r(float x) { return __uint_as_float(f2tf32(x)); }
__device__ __forceinline__ void mma8(float* c, const uint32_t* a, const uint32_t* b) {
    asm volatile(
        "mma.sync.aligned.m16n8k8.row.col.f32.tf32.tf32.f32 "
        "{%0,%1,%2,%3},{%4,%5,%6,%7},{%8,%9},{%0,%1,%2,%3};"
        : "+f"(c[0]), "+f"(c[1]), "+f"(c[2]), "+f"(c[3])
        : "r"(a[0]), "r"(a[1]), "r"(a[2]), "r"(a[3]), "r"(b[0]), "r"(b[1]));
}
__device__ __forceinline__ void mma16(float* c, const uint32_t* a, const uint32_t* b) {
    asm volatile(
        "mma.sync.aligned.m16n8k16.row.col.f32.bf16.bf16.f32 "
        "{%0,%1,%2,%3},{%4,%5,%6,%7},{%8,%9},{%0,%1,%2,%3};"
        : "+f"(c[0]), "+f"(c[1]), "+f"(c[2]), "+f"(c[3])
        : "r"(a[0]), "r"(a[1]), "r"(a[2]), "r"(a[3]), "r"(b[0]), "r"(b[1]));
}
__device__ __forceinline__ unsigned fenc(float f) {
    unsigned u = __float_as_uint(f);
    return u ^ ((u >> 31) ? 0xFFFFFFFFu : 0x80000000u);
}
__device__ __forceinline__ float fdec(unsigned u) {
    return __uint_as_float(u ^ ((u & 0x80000000u) ? 0x80000000u : 0xFFFFFFFFu));
}
__device__ __forceinline__ void cpa16(uint32_t dst, const void* src) {
    asm volatile("cp.async.ca.shared.global [%0], [%1], 16;" :: "r"(dst), "l"(src));
}
#define CP_COMMIT() asm volatile("cp.async.commit_group;")
#define CP_WAIT0()  asm volatile("cp.async.wait_group 0;")
__device__ __forceinline__ uint32_t packbf(float lo, float hi) {
    __nv_bfloat162 p = __floats2bfloat162_rn(lo, hi);
    return *reinterpret_cast<uint32_t*>(&p);
}

// ---------------- pack adjacency to transposed bits (int4 + or-reduce) -------
__global__ __launch_bounds__(256) void pack_k(const int* __restrict__ adj,
                                              unsigned* __restrict__ bitsT,
                                              unsigned* __restrict__ Tenc)
{
    int i = blockIdx.x;
    int t = threadIdx.x, lane = t & 31, w = t >> 5;
    if (i == 0 && t < NH + 1) Tenc[t] = 0u;
    for (int base = w * 128; base < NN; base += 8 * 128) {
        int4 a = *(const int4*)(adj + (size_t)i * NN + base + lane * 4);
        unsigned nib = (unsigned)(a.x > 0) | ((unsigned)(a.y > 0) << 1)
                     | ((unsigned)(a.z > 0) << 2) | ((unsigned)(a.w > 0) << 3);
        unsigned v = nib << (4 * (lane & 7));
        v |= __shfl_xor_sync(0xffffffffu, v, 1);
        v |= __shfl_xor_sync(0xffffffffu, v, 2);
        v |= __shfl_xor_sync(0xffffffffu, v, 4);
        if ((lane & 7) == 0)
            bitsT[(size_t)((base >> 5) + (lane >> 3)) * NN + i] = v;
    }
}

// ---------------- stage1 feature GEMM (tf32 mma, BM=32, 512 blocks) ----------
// BM=32, BN=128, BK=16, 128 threads, warps 2Mx2N (warp tile 16x64).
__global__ __launch_bounds__(128) void gemm1_k(
    const float* __restrict__ A, const float* __restrict__ W,
    const float* __restrict__ bias, float* __restrict__ C)
{
    __shared__ float As[2][16][72];
    __shared__ float Bs[2][16][136];
    const int head = blockIdx.y;
    const int rowBase = blockIdx.x * 32;
    const int t = threadIdx.x;
    const int lane = t & 31, wid = t >> 5;
    const int gid = lane >> 2, tig = lane & 3;
    const int mw = wid >> 1, nw = wid & 1;
    const float* Wh = W + (size_t)head * FIN * FH;
    const int arow = t & 31, akg = (t >> 5) << 2;   // row = lane, 4-col group per warp

    float acc[8][4] = {};
    float ar[4], br[16];

    auto LDG = [&](int k0) {
        float4 a0 = *(const float4*)(A + (size_t)(rowBase + arow) * FIN + k0 + akg);
        ar[0] = a0.x; ar[1] = a0.y; ar[2] = a0.z; ar[3] = a0.w;
        #pragma unroll
        for (int v = 0; v < 4; v++) {
            int idx = t + v * 128;
            int kr = idx >> 5, cc = (idx & 31) << 2;
            float4 b = *(const float4*)(Wh + (size_t)(k0 + kr) * FH + cc);
            br[4 * v + 0] = b.x; br[4 * v + 1] = b.y;
            br[4 * v + 2] = b.z; br[4 * v + 3] = b.w;
        }
    };
    auto STS = [&](int bb) {
        #pragma unroll
        for (int q = 0; q < 4; q++) As[bb][akg + q][arow] = tf32r(ar[q]);
        #pragma unroll
        for (int v = 0; v < 4; v++) {
            int idx = t + v * 128;
            int kr = idx >> 5, cc = (idx & 31) << 2;
            float4 o = {tf32r(br[4 * v]), tf32r(br[4 * v + 1]),
                        tf32r(br[4 * v + 2]), tf32r(br[4 * v + 3])};
            *(float4*)&Bs[bb][kr][cc] = o;
        }
    };

    LDG(0); STS(0);
    __syncthreads();
    const int NIT = FIN / 16;
    for (int n = 0; n < NIT; n++) {
        const int b = n & 1;
        if (n + 1 < NIT) LDG((n + 1) * 16);
        #pragma unroll
        for (int kc = 0; kc < 2; kc++) {
            int kk = kc * 8;
            int rb = mw * 16;
            uint32_t af[4];
            af[0] = __float_as_uint(As[b][kk + tig][rb + gid]);
            af[1] = __float_as_uint(As[b][kk + tig][rb + gid + 8]);
            af[2] = __float_as_uint(As[b][kk + tig + 4][rb + gid]);
            af[3] = __float_as_uint(As[b][kk + tig + 4][rb + gid + 8]);
            #pragma unroll
            for (int nt = 0; nt < 8; nt++) {
                int cb = nw * 64 + nt * 8;
                uint32_t bf[2];
                bf[0] = __float_as_uint(Bs[b][kk + tig][cb + gid]);
                bf[1] = __float_as_uint(Bs[b][kk + tig + 4][cb + gid]);
                mma8(acc[nt], af, bf);
            }
        }
        if (n + 1 < NIT) STS(b ^ 1);
        __syncthreads();
    }
    {
        int r0 = rowBase + mw * 16 + gid;
        #pragma unroll
        for (int nt = 0; nt < 8; nt++) {
            int c0 = nw * 64 + nt * 8 + tig * 2;
            float b0 = bias[head * FH + c0], b1 = bias[head * FH + c0 + 1];
            float2 lo = {acc[nt][0] + b0, acc[nt][1] + b1};
            float2 hi = {acc[nt][2] + b0, acc[nt][3] + b1};
            *(float2*)(C + (size_t)r0 * FCAT + head * FH + c0) = lo;
            *(float2*)(C + (size_t)(r0 + 8) * FCAT + head * FH + c0) = hi;
        }
    }
}

// ---------------- fused logits + global max + B pairs + bf16 pack ------------
template <int COLS, int NHH>
__global__ __launch_bounds__(256) void sdotpack_k(
    const float* __restrict__ Hmat,
    const float* __restrict__ a1, const float* __restrict__ a2,
    const float* __restrict__ ab,
    float* __restrict__ s1, float2* __restrict__ Bp,
    unsigned* __restrict__ Tenc, uint32_t* __restrict__ Hp)
{
    const int F = COLS / NHH;
    __shared__ float rows[8][COLS];
    __shared__ float sa1[COLS], sa2[COLS];
    const int i0 = blockIdx.x * 8;
    const int t = threadIdx.x;
    for (int c = t; c < COLS; c += 256) { sa1[c] = a1[c]; sa2[c] = a2[c]; }
    for (int idx = t * 4; idx < 8 * COLS; idx += 1024) {
        int r = idx / COLS, c = idx % COLS;
        *(float4*)&rows[r][c] = *(const float4*)(Hmat + (size_t)(i0 + r) * COLS + c);
    }
    __syncthreads();

    const int w = t >> 5, lane = t & 31;
    float d1h[NHH], d2h[NHH];
    #pragma unroll
    for (int h = 0; h < NHH; h++) { d1h[h] = 0.f; d2h[h] = 0.f; }
    #pragma unroll
    for (int q = 0; q < COLS / 32; q++) {
        int c = lane + 32 * q;
        int h = q / (F / 32);
        float v = rows[w][c];
        d1h[h] = fmaf(v, sa1[c], d1h[h]);
        d2h[h] = fmaf(v, sa2[c], d2h[h]);
    }
    #pragma unroll
    for (int h = 0; h < NHH; h++) {
        #pragma unroll
        for (int off = 16; off; off >>= 1) {
            d1h[h] += __shfl_xor_sync(0xffffffffu, d1h[h], off);
            d2h[h] += __shfl_xor_sync(0xffffffffu, d2h[h], off);
        }
    }
    if (lane == 0) {
        int i = i0 + w;
        #pragma unroll
        for (int h = 0; h < NHH; h++) {
            s1[h * NN + i] = d1h[h];
            float tv = d2h[h] + ab[h];
            atomicMax(&Tenc[h], fenc(tv));
            Bp[h * NN + i] = make_float2(__expf(tv), __expf(0.2f * tv));
        }
    }
    for (int idx = t; idx < 4 * COLS; idx += 256) {
        int p = idx / COLS, c = idx % COLS;
        Hp[(size_t)(i0 / 2 + p) * COLS + c] = packbf(rows[2 * p][c], rows[2 * p + 1][c]);
    }
}

// ---------------- stage1 aggregation: bf16 mma, 256 thr, BK=32 ---------------
// BM=64, BN=128, BK=32. grid (NN/64, NH, JS1)
__global__ __launch_bounds__(256) void agg1_k(
    const unsigned* __restrict__ bitsT,
    const float* __restrict__ s1a,
    const float2* __restrict__ Bp,
    const unsigned* __restrict__ Tg,
    const uint32_t* __restrict__ Hp,
    float* __restrict__ part, float* __restrict__ psums)
{
    const int SL = NN / JS1;                       // 1024
    __shared__ __align__(16) uint32_t Ps2[2][16][72];
    __shared__ __align__(16) uint32_t Hs2[2][16][136];
    __shared__ __align__(16) float2 sBp[SL];       // 8 KB
    __shared__ unsigned sbits[64][33];             // 8.4 KB
    __shared__ float spart[4][64];

    const int head = blockIdx.y;
    const int i0 = blockIdx.x * 64;
    const int kb = blockIdx.z;
    const int t = threadIdx.x;
    const int lane = t & 31, wid = t >> 5;
    const int gid = lane >> 2, tig = lane & 3;
    const int mw = wid >> 2, nwq = wid & 3;
    const int r = t & 63, quarter = t >> 6;
    const int js = kb * SL;

    float T = fdec(Tg[head]);
    float s1v = s1a[head * NN + i0 + r];
    float zz = s1v + T;
    float cc = fmaxf(zz, 0.2f * zz);
    float Av  = __expf(s1v - cc);
    float A2v = __expf(0.2f * s1v - cc);

    {
        const float2* BpH = Bp + head * NN + js;
        for (int q = t; q < SL; q += 256) sBp[q] = BpH[q];
        #pragma unroll
        for (int k = 0; k < SL / 32; k += 4) {
            int w = quarter + k;
            sbits[r][w] = bitsT[(size_t)(js / 32 + w) * NN + i0 + r];
        }
    }
    uint32_t hs0 = (uint32_t)__cvta_generic_to_shared(&Hs2[0][0][0]);
    __syncthreads();

    float acc[2][4][4] = {};
    float psum = 0.f;
    const int NCH = SL / 32;                       // 32 chunks

    auto fill = [&](int n, int b) {
        int jl = n * 32;
        unsigned w = sbits[r][n];
        unsigned hw = w >> (quarter * 8);
        const float4* bv = (const float4*)(&sBp[jl + quarter * 8]);
        #pragma unroll
        for (int q = 0; q < 4; q++) {
            float4 f = bv[q];
            float p0 = fmaxf(Av * f.x, A2v * f.y);
            float p1 = fmaxf(Av * f.z, A2v * f.w);
            int m0 = ((int)(hw << (31 - 2 * q))) >> 31;
            int m1 = ((int)(hw << (30 - 2 * q))) >> 31;
            p0 = __uint_as_float(__float_as_uint(p0) & (unsigned)m0);
            p1 = __uint_as_float(__float_as_uint(p1) & (unsigned)m1);
            __nv_bfloat162 pb = __floats2bfloat162_rn(p0, p1);
            psum += __low2float(pb) + __high2float(pb);
            Ps2[b][quarter * 4 + q][r] = *reinterpret_cast<uint32_t*>(&pb);
        }
        const uint32_t* hsrc = Hp + (size_t)((js + jl) >> 1) * FCAT + head * FH;
        uint32_t hb = hs0 + (uint32_t)b * (16 * 136 * 4);
        #pragma unroll
        for (int v = 0; v < 2; v++) {
            int idx = t + v * 256;
            int kr = idx >> 5, c16 = idx & 31;
            cpa16(hb + kr * (136 * 4) + c16 * 16,
                  hsrc + (size_t)kr * FCAT + c16 * 4);
        }
    };

    fill(0, 0);
    CP_COMMIT();
    CP_WAIT0();
    __syncthreads();
    for (int n = 0; n < NCH; n++) {
        const int b = n & 1;
        if (n + 1 < NCH) { fill(n + 1, b ^ 1); CP_COMMIT(); }
        #pragma unroll
        for (int ks = 0; ks < 2; ks++) {
            int kk = ks * 8;
            uint32_t af[2][4];
            #pragma unroll
            for (int mt = 0; mt < 2; mt++) {
                int rb = mw * 32 + mt * 16;
                af[mt][0] = Ps2[b][kk + tig][rb + gid];
                af[mt][1] = Ps2[b][kk + tig][rb + gid + 8];
                af[mt][2] = Ps2[b][kk + tig + 4][rb + gid];
                af[mt][3] = Ps2[b][kk + tig + 4][rb + gid + 8];
            }
            #pragma unroll
            for (int nt = 0; nt < 4; nt++) {
                int cb = nwq * 32 + nt * 8;
                uint32_t bf[2];
                bf[0] = Hs2[b][kk + tig][cb + gid];
                bf[1] = Hs2[b][kk + tig + 4][cb + gid];
                mma16(acc[0][nt], af[0], bf);
                mma16(acc[1][nt], af[1], bf);
            }
        }
        CP_WAIT0();
        __syncthreads();
    }
    spart[quarter][r] = psum;
    __syncthreads();
    if (t < 64)
        psums[((size_t)kb * NH + head) * NN + i0 + t] =
            spart[0][t] + spart[1][t] + spart[2][t] + spart[3][t];
    float* pb = part + (size_t)kb * NN * FCAT;
    #pragma unroll
    for (int mt = 0; mt < 2; mt++) {
        int r0 = i0 + mw * 32 + mt * 16 + gid;
        #pragma unroll
        for (int nt = 0; nt < 4; nt++) {
            int c0 = head * FH + nwq * 32 + nt * 8 + tig * 2;
            float2 lo = {acc[mt][nt][0], acc[mt][nt][1]};
            float2 hi = {acc[mt][nt][2], acc[mt][nt][3]};
            *(float2*)(pb + (size_t)r0 * FCAT + c0) = lo;
            *(float2*)(pb + (size_t)(r0 + 8) * FCAT + c0) = hi;
        }
    }
}

// ---------------- stage1 combine: normalize + elu -> x2 ----------------------
__global__ __launch_bounds__(128) void combine1_k(
    const float* __restrict__ p1, const float* __restrict__ sp1,
    float* __restrict__ x2)
{
    int i = blockIdx.x, t = threadIdx.x;
    int c = t * 4;
    int head = c >> 7;
    float s = 0.f;
    #pragma unroll
    for (int k = 0; k < JS1; k++)
        s += sp1[((size_t)k * NH + head) * NN + i];
    float inv = 1.f / s;
    float4 acc = {0.f, 0.f, 0.f, 0.f};
    #pragma unroll
    for (int k = 0; k < JS1; k++) {
        float4 a = *(const float4*)(p1 + (size_t)k * NN * FCAT + (size_t)i * FCAT + c);
        acc.x += a.x; acc.y += a.y; acc.z += a.z; acc.w += a.w;
    }
    float4 o; float v;
    v = acc.x * inv; o.x = v > 0.f ? v : expm1f(v);
    v = acc.y * inv; o.y = v > 0.f ? v : expm1f(v);
    v = acc.z * inv; o.z = v > 0.f ? v : expm1f(v);
    v = acc.w * inv; o.w = v > 0.f ? v : expm1f(v);
    *(float4*)(x2 + (size_t)i * FCAT + c) = o;
}

// ---------------- stage2 feature GEMM (tf32 mma, reg double buffer) ----------
__global__ __launch_bounds__(128) void gemm2_k(
    const float* __restrict__ A, const float* __restrict__ W,
    const float* __restrict__ bias, float* __restrict__ C)
{
    __shared__ float As[2][16][72];
    __shared__ float Bs[2][16][72];
    const int rowBase = blockIdx.x * 64;
    const int t = threadIdx.x;
    const int lane = t & 31, wid = t >> 5;
    const int gid = lane >> 2, tig = lane & 3;
    const int mw = wid >> 1, nw = wid & 1;
    const int arow = t >> 1, akc = (t & 1) << 3;

    float acc[2][4][4] = {};
    float ar[8], br[8];

    auto LDG = [&](int k0) {
        float4 a0 = *(const float4*)(A + (size_t)(rowBase + arow) * FCAT + k0 + akc);
        float4 a1 = *(const float4*)(A + (size_t)(rowBase + arow) * FCAT + k0 + akc + 4);
        ar[0] = a0.x; ar[1] = a0.y; ar[2] = a0.z; ar[3] = a0.w;
        ar[4] = a1.x; ar[5] = a1.y; ar[6] = a1.z; ar[7] = a1.w;
        #pragma unroll
        for (int v = 0; v < 2; v++) {
            int idx = t + v * 128;
            int kr = idx >> 4, cc = (idx & 15) << 2;
            float4 b = *(const float4*)(W + (size_t)(k0 + kr) * FOUT + cc);
            br[4 * v + 0] = b.x; br[4 * v + 1] = b.y;
            br[4 * v + 2] = b.z; br[4 * v + 3] = b.w;
        }
    };
    auto STS = [&](int bb) {
        #pragma unroll
        for (int q = 0; q < 8; q++) As[bb][akc + q][arow] = tf32r(ar[q]);
        #pragma unroll
        for (int v = 0; v < 2; v++) {
            int idx = t + v * 128;
            int kr = idx >> 4, cc = (idx & 15) << 2;
            float4 o = {tf32r(br[4 * v]), tf32r(br[4 * v + 1]),
                        tf32r(br[4 * v + 2]), tf32r(br[4 * v + 3])};
            *(float4*)&Bs[bb][kr][cc] = o;
        }
    };

    LDG(0); STS(0);
    __syncthreads();
    const int NIT = FCAT / 16;
    for (int n = 0; n < NIT; n++) {
        const int b = n & 1;
        if (n + 1 < NIT) LDG((n + 1) * 16);
        #pragma unroll
        for (int kc = 0; kc < 2; kc++) {
            int kk = kc * 8;
            uint32_t af[2][4];
            #pragma unroll
            for (int mt = 0; mt < 2; mt++) {
                int rb = mw * 32 + mt * 16;
                af[mt][0] = __float_as_uint(As[b][kk + tig][rb + gid]);
                af[mt][1] = __float_as_uint(As[b][kk + tig][rb + gid + 8]);
                af[mt][2] = __float_as_uint(As[b][kk + tig + 4][rb + gid]);
                af[mt][3] = __float_as_uint(As[b][kk + tig + 4][rb + gid + 8]);
            }
            #pragma unroll
            for (int nt = 0; nt < 4; nt++) {
                int cb = nw * 32 + nt * 8;
                uint32_t bf[2];
                bf[0] = __float_as_uint(Bs[b][kk + tig][cb + gid]);
                bf[1] = __float_as_uint(Bs[b][kk + tig + 4][cb + gid]);
                mma8(acc[0][nt], af[0], bf);
                mma8(acc[1][nt], af[1], bf);
            }
        }
        if (n + 1 < NIT) STS(b ^ 1);
        __syncthreads();
    }
    #pragma unroll
    for (int mt = 0; mt < 2; mt++) {
        int r0 = rowBase + mw * 32 + mt * 16 + gid;
        #pragma unroll
        for (int nt = 0; nt < 4; nt++) {
            int c0 = nw * 32 + nt * 8 + tig * 2;
            float b0 = bias[c0], b1 = bias[c0 + 1];
            float2 lo = {acc[mt][nt][0] + b0, acc[mt][nt][1] + b1};
            float2 hi = {acc[mt][nt][2] + b0, acc[mt][nt][3] + b1};
            *(float2*)(C + (size_t)r0 * FOUT + c0) = lo;
            *(float2*)(C + (size_t)(r0 + 8) * FOUT + c0) = hi;
        }
    }
}

// ---------------- stage2 aggregation split-K (bf16 mma, 256 thr, BK=32) -----
// BM=64, BN=64, BK=32. grid (NN/64, JS2)
__global__ __launch_bounds__(256) void agg2_k(
    const unsigned* __restrict__ bitsT,
    const float* __restrict__ s1a,
    const float2* __restrict__ Bp,
    const unsigned* __restrict__ Tg,
    const uint32_t* __restrict__ Hp,
    float* __restrict__ part, float* __restrict__ psums)
{
    const int SL = NN / JS2;                       // 512
    __shared__ __align__(16) uint32_t Ps2[2][16][72];
    __shared__ __align__(16) uint32_t Hs2[2][16][72];
    __shared__ __align__(16) float2 sBp[SL];
    __shared__ unsigned sbits[64][17];
    __shared__ float spart[4][64];

    const int i0 = blockIdx.x * 64;
    const int kb = blockIdx.y;
    const int t = threadIdx.x;
    const int lane = t & 31, wid = t >> 5;
    const int gid = lane >> 2, tig = lane & 3;
    const int mw = wid >> 2, nwq = wid & 3;
    const int r = t & 63, quarter = t >> 6;
    const int js = kb * SL;

    float T = fdec(Tg[0]);
    float s1v = s1a[i0 + r];
    float zz = s1v + T;
    float cc = fmaxf(zz, 0.2f * zz);
    float Av  = __expf(s1v - cc);
    float A2v = __expf(0.2f * s1v - cc);

    {
        const float2* BpS = Bp + js;
        for (int q = t; q < SL; q += 256) sBp[q] = BpS[q];
        #pragma unroll
        for (int k = 0; k < SL / 32; k += 4) {
            int w = quarter + k;
            sbits[r][w] = bitsT[(size_t)(js / 32 + w) * NN + i0 + r];
        }
    }
    uint32_t hs0 = (uint32_t)__cvta_generic_to_shared(&Hs2[0][0][0]);
    __syncthreads();

    float acc[2][2][4] = {};
    float psum = 0.f;
    const int NCH = SL / 32;                       // 16 chunks

    auto fill = [&](int n, int b) {
        int jl = n * 32;
        unsigned w = sbits[r][n];
        unsigned hw = w >> (quarter * 8);
        const float4* bv = (const float4*)(&sBp[jl + quarter * 8]);
        #pragma unroll
        for (int q = 0; q < 4; q++) {
            float4 f = bv[q];
            float p0 = fmaxf(Av * f.x, A2v * f.y);
            float p1 = fmaxf(Av * f.z, A2v * f.w);
            int m0 = ((int)(hw << (31 - 2 * q))) >> 31;
            int m1 = ((int)(hw << (30 - 2 * q))) >> 31;
            p0 = __uint_as_float(__float_as_uint(p0) & (unsigned)m0);
            p1 = __uint_as_float(__float_as_uint(p1) & (unsigned)m1);
            __nv_bfloat162 pb = __floats2bfloat162_rn(p0, p1);
            psum += __low2float(pb) + __high2float(pb);
            Ps2[b][quarter * 4 + q][r] = *reinterpret_cast<uint32_t*>(&pb);
        }
        const uint32_t* hsrc = Hp + (size_t)((js + jl) >> 1) * FOUT;
        uint32_t hb = hs0 + (uint32_t)b * (16 * 72 * 4);
        {
            int kr = t >> 4, c16 = t & 15;
            cpa16(hb + kr * (72 * 4) + c16 * 16,
                  hsrc + (size_t)kr * FOUT + c16 * 4);
        }
    };

    fill(0, 0);
    CP_COMMIT();
    CP_WAIT0();
    __syncthreads();
    for (int n = 0; n < NCH; n++) {
        const int b = n & 1;
        if (n + 1 < NCH) { fill(n + 1, b ^ 1); CP_COMMIT(); }
        #pragma unroll
        for (int ks = 0; ks < 2; ks++) {
            int kk = ks * 8;
            uint32_t af[2][4];
            #pragma unroll
            for (int mt = 0; mt < 2; mt++) {
                int rb = mw * 32 + mt * 16;
                af[mt][0] = Ps2[b][kk + tig][rb + gid];
                af[mt][1] = Ps2[b][kk + tig][rb + gid + 8];
                af[mt][2] = Ps2[b][kk + tig + 4][rb + gid];
                af[mt][3] = Ps2[b][kk + tig + 4][rb + gid + 8];
            }
            #pragma unroll
            for (int nt = 0; nt < 2; nt++) {
                int cb = nwq * 16 + nt * 8;
                uint32_t bf[2];
                bf[0] = Hs2[b][kk + tig][cb + gid];
                bf[1] = Hs2[b][kk + tig + 4][cb + gid];
                mma16(acc[0][nt], af[0], bf);
                mma16(acc[1][nt], af[1], bf);
            }
        }
        CP_WAIT0();
        __syncthreads();
    }
    spart[quarter][r] = psum;
    __syncthreads();
    if (t < 64)
        psums[(size_t)kb * NN + i0 + t] =
            spart[0][t] + spart[1][t] + spart[2][t] + spart[3][t];
    float* pb = part + (size_t)kb * NN * FOUT;
    #pragma unroll
    for (int mt = 0; mt < 2; mt++) {
        int r0 = i0 + mw * 32 + mt * 16 + gid;
        #pragma unroll
        for (int nt = 0; nt < 2; nt++) {
            int c0 = nwq * 16 + nt * 8 + tig * 2;
            float2 lo = {acc[mt][nt][0], acc[mt][nt][1]};
            float2 hi = {acc[mt][nt][2], acc[mt][nt][3]};
            *(float2*)(pb + (size_t)r0 * FOUT + c0) = lo;
            *(float2*)(pb + (size_t)(r0 + 8) * FOUT + c0) = hi;
        }
    }
}

// ---------------- combine partials + normalize + elu + log_softmax ----------
__global__ void combine_k(const float* __restrict__ part,
                          const float* __restrict__ psums,
                          float* __restrict__ out)
{
    int i = blockIdx.x, c = threadIdx.x;  // 64 threads
    float v = 0.f, s = 0.f;
    #pragma unroll
    for (int k = 0; k < JS2; k++) {
        v += part[(size_t)k * NN * FOUT + (size_t)i * FOUT + c];
        s += psums[(size_t)k * NN + i];
    }
    v /= s;
    float e = v > 0.f ? v : expm1f(v);
    __shared__ float sh[4];
    float m = e;
    #pragma unroll
    for (int off = 16; off; off >>= 1)
        m = fmaxf(m, __shfl_xor_sync(0xffffffffu, m, off));
    if ((c & 31) == 0) sh[c >> 5] = m;
    __syncthreads();
    m = fmaxf(sh[0], sh[1]);
    float se = expf(e - m);
    #pragma unroll
    for (int off = 16; off; off >>= 1)
        se += __shfl_xor_sync(0xffffffffu, se, off);
    if ((c & 31) == 0) sh[2 + (c >> 5)] = se;
    __syncthreads();
    se = sh[2] + sh[3];
    out[(size_t)i * FOUT + c] = e - (m + logf(se));
}

// ---------------- launch -----------------------------------------------------
extern "C" void kernel_launch(void* const* d_in, const int* in_sizes, int n_in,
                              void* d_out, int out_size)
{
    const float* X    = (const float*)d_in[0];
    const int*   adj  = (const int*)  d_in[1];
    const float* W_h  = (const float*)d_in[2];
    const float* b_h  = (const float*)d_in[3];
    const float* a1_h = (const float*)d_in[4];
    const float* a2_h = (const float*)d_in[5];
    const float* ab_h = (const float*)d_in[6];
    const float* W_o  = (const float*)d_in[7];
    const float* b_o  = (const float*)d_in[8];
    const float* a1_o = (const float*)d_in[9];
    const float* a2_o = (const float*)d_in[10];
    const float* ab_o = (const float*)d_in[11];
    float* out = (float*)d_out;

    unsigned *bitsT, *Tenc;
    uint32_t *Hp1, *Hp2;
    float *hcat, *x2, *h2, *s1, *s1o, *p1, *sp1, *p2, *sp2;
    float2 *Bp1, *Bp2;
    cudaGetSymbolAddress((void**)&bitsT, g_bitsT);
    cudaGetSymbolAddress((void**)&Tenc,  g_Tenc);
    cudaGetSymbolAddress((void**)&hcat,  g_hcat);
    cudaGetSymbolAddress((void**)&x2,    g_x2);
    cudaGetSymbolAddress((void**)&h2,    g_h2);
    cudaGetSymbolAddress((void**)&Hp1,   g_Hp1);
    cudaGetSymbolAddress((void**)&Hp2,   g_Hp2);
    cudaGetSymbolAddress((void**)&s1,    g_s1);
    cudaGetSymbolAddress((void**)&s1o,   g_s1o);
    cudaGetSymbolAddress((void**)&Bp1,   g_Bp1);
    cudaGetSymbolAddress((void**)&Bp2,   g_Bp2);
    cudaGetSymbolAddress((void**)&p1,    g_p1);
    cudaGetSymbolAddress((void**)&sp1,   g_sp1);
    cudaGetSymbolAddress((void**)&p2,    g_p2);
    cudaGetSymbolAddress((void**)&sp2,   g_sp2);

    pack_k<<<NN, 256>>>(adj, bitsT, Tenc);

    {   dim3 grid(NN / 32, NH);
        gemm1_k<<<grid, 128>>>(X, W_h, b_h, hcat); }

    sdotpack_k<FCAT, NH><<<NN / 8, 256>>>(hcat, a1_h, a2_h, ab_h,
                                          s1, Bp1, Tenc, Hp1);

    {   dim3 grid(NN / 64, NH, JS1);
        agg1_k<<<grid, 256>>>(bitsT, s1, Bp1, Tenc, Hp1, p1, sp1); }

    combine1_k<<<NN, 128>>>(p1, sp1, x2);

    gemm2_k<<<NN / 64, 128>>>(x2, W_o, b_o, h2);

    sdotpack_k<FOUT, 1><<<NN / 8, 256>>>(h2, a1_o, a2_o, ab_o,
                                         s1o, Bp2, Tenc + NH, Hp2);

    {   dim3 grid(NN / 64, JS2);
        agg2_k<<<grid, 256>>>(bitsT, s1o, Bp2, Tenc + NH, Hp2, p2, sp2); }

    combine_k<<<NN, 64>>>(p2, sp2, out);
}

// round 17
// speedup vs baseline: 1.1129x; 1.0446x over previous
#include <cuda_runtime.h>
#include <cuda_bf16.h>
#include <math.h>
#include <stdint.h>

#define NN    4096
#define FIN   512
#define FH    128
#define NH    4
#define FOUT  64
#define FCAT  512
#define JS1   4
#define JS2   8

// ---------------- scratch ----------------------------------------------------
__device__ unsigned g_bitsT[NN * NN / 32];     // bitsT[(j>>5)*NN + i]
__device__ float  g_hcat[NN * FCAT];
__device__ float  g_x2  [NN * FCAT];
__device__ float  g_h2  [NN * FOUT];
__device__ uint32_t g_Hp1[(NN / 2) * FCAT];    // bf16x2 k-packed hcat
__device__ uint32_t g_Hp2[(NN / 2) * FOUT];    // bf16x2 k-packed h2
__device__ float  g_s1  [NH * NN];
__device__ float  g_s1o [NN];
__device__ float2 g_Bp1 [NH * NN];             // (exp(t2), exp(0.2*t2))
__device__ float2 g_Bp2 [NN];
__device__ unsigned g_Tenc[NH + 1];
__device__ float  g_p1  [JS1 * NN * FCAT];
__device__ float  g_sp1 [JS1 * NH * NN];
__device__ float  g_p2  [JS2 * NN * FOUT];
__device__ float  g_sp2 [JS2 * NN];

// ---------------- helpers ----------------------------------------------------
__device__ __forceinline__ uint32_t f2tf32(float x) {
    uint32_t r;
    asm("cvt.rna.tf32.f32 %0, %1;" : "=r"(r) : "f"(x));
    return r;
}
__device__ __forceinline__ float tf32r(float x) { return __uint_as_float(f2tf32(x)); }
__device__ __forceinline__ void mma8(float* c, const uint32_t* a, const uint32_t* b) {
    asm volatile(
        "mma.sync.aligned.m16n8k8.row.col.f32.tf32.tf32.f32 "
        "{%0,%1,%2,%3},{%4,%5,%6,%7},{%8,%9},{%0,%1,%2,%3};"
        : "+f"(c[0]), "+f"(c[1]), "+f"(c[2]), "+f"(c[3])
        : "r"(a[0]), "r"(a[1]), "r"(a[2]), "r"(a[3]), "r"(b[0]), "r"(b[1]));
}
__device__ __forceinline__ void mma16(float* c, const uint32_t* a, const uint32_t* b) {
    asm volatile(
        "mma.sync.aligned.m16n8k16.row.col.f32.bf16.bf16.f32 "
        "{%0,%1,%2,%3},{%4,%5,%6,%7},{%8,%9},{%0,%1,%2,%3};"
        : "+f"(c[0]), "+f"(c[1]), "+f"(c[2]), "+f"(c[3])
        : "r"(a[0]), "r"(a[1]), "r"(a[2]), "r"(a[3]), "r"(b[0]), "r"(b[1]));
}
__device__ __forceinline__ unsigned fenc(float f) {
    unsigned u = __float_as_uint(f);
    return u ^ ((u >> 31) ? 0xFFFFFFFFu : 0x80000000u);
}
__device__ __forceinline__ float fdec(unsigned u) {
    return __uint_as_float(u ^ ((u & 0x80000000u) ? 0x80000000u : 0xFFFFFFFFu));
}
__device__ __forceinline__ void cpa16(uint32_t dst, const void* src) {
    asm volatile("cp.async.ca.shared.global [%0], [%1], 16;" :: "r"(dst), "l"(src));
}
#define CP_COMMIT() asm volatile("cp.async.commit_group;")
#define CP_WAIT0()  asm volatile("cp.async.wait_group 0;")
__device__ __forceinline__ uint32_t packbf(float lo, float hi) {
    __nv_bfloat162 p = __floats2bfloat162_rn(lo, hi);
    return *reinterpret_cast<uint32_t*>(&p);
}

// ---------------- pack adjacency to transposed bits (int4 + or-reduce) -------
__global__ __launch_bounds__(256) void pack_k(const int* __restrict__ adj,
                                              unsigned* __restrict__ bitsT,
                                              unsigned* __restrict__ Tenc)
{
    int i = blockIdx.x;
    int t = threadIdx.x, lane = t & 31, w = t >> 5;
    if (i == 0 && t < NH + 1) Tenc[t] = 0u;
    for (int base = w * 128; base < NN; base += 8 * 128) {
        int4 a = *(const int4*)(adj + (size_t)i * NN + base + lane * 4);
        unsigned nib = (unsigned)(a.x > 0) | ((unsigned)(a.y > 0) << 1)
                     | ((unsigned)(a.z > 0) << 2) | ((unsigned)(a.w > 0) << 3);
        unsigned v = nib << (4 * (lane & 7));
        v |= __shfl_xor_sync(0xffffffffu, v, 1);
        v |= __shfl_xor_sync(0xffffffffu, v, 2);
        v |= __shfl_xor_sync(0xffffffffu, v, 4);
        if ((lane & 7) == 0)
            bitsT[(size_t)((base >> 5) + (lane >> 3)) * NN + i] = v;
    }
}

// ---------------- stage1 feature GEMM (tf32 mma, reg double buffer) ----------
__global__ __launch_bounds__(128) void gemm1_k(
    const float* __restrict__ A, const float* __restrict__ W,
    const float* __restrict__ bias, float* __restrict__ C)
{
    __shared__ float As[2][16][72];
    __shared__ float Bs[2][16][136];
    const int head = blockIdx.y;
    const int rowBase = blockIdx.x * 64;
    const int t = threadIdx.x;
    const int lane = t & 31, wid = t >> 5;
    const int gid = lane >> 2, tig = lane & 3;
    const int mw = wid >> 1, nw = wid & 1;
    const float* Wh = W + (size_t)head * FIN * FH;
    const int arow = t >> 1, akc = (t & 1) << 3;

    float acc[2][8][4] = {};
    float ar[8], br[16];

    auto LDG = [&](int k0) {
        float4 a0 = *(const float4*)(A + (size_t)(rowBase + arow) * FIN + k0 + akc);
        float4 a1 = *(const float4*)(A + (size_t)(rowBase + arow) * FIN + k0 + akc + 4);
        ar[0] = a0.x; ar[1] = a0.y; ar[2] = a0.z; ar[3] = a0.w;
        ar[4] = a1.x; ar[5] = a1.y; ar[6] = a1.z; ar[7] = a1.w;
        #pragma unroll
        for (int v = 0; v < 4; v++) {
            int idx = t + v * 128;
            int kr = idx >> 5, cc = (idx & 31) << 2;
            float4 b = *(const float4*)(Wh + (size_t)(k0 + kr) * FH + cc);
            br[4 * v + 0] = b.x; br[4 * v + 1] = b.y;
            br[4 * v + 2] = b.z; br[4 * v + 3] = b.w;
        }
    };
    auto STS = [&](int bb) {
        #pragma unroll
        for (int q = 0; q < 8; q++) As[bb][akc + q][arow] = tf32r(ar[q]);
        #pragma unroll
        for (int v = 0; v < 4; v++) {
            int idx = t + v * 128;
            int kr = idx >> 5, cc = (idx & 31) << 2;
            float4 o = {tf32r(br[4 * v]), tf32r(br[4 * v + 1]),
                        tf32r(br[4 * v + 2]), tf32r(br[4 * v + 3])};
            *(float4*)&Bs[bb][kr][cc] = o;
        }
    };

    LDG(0); STS(0);
    __syncthreads();
    const int NIT = FIN / 16;
    for (int n = 0; n < NIT; n++) {
        const int b = n & 1;
        if (n + 1 < NIT) LDG((n + 1) * 16);
        #pragma unroll
        for (int kc = 0; kc < 2; kc++) {
            int kk = kc * 8;
            uint32_t af[2][4];
            #pragma unroll
            for (int mt = 0; mt < 2; mt++) {
                int rb = mw * 32 + mt * 16;
                af[mt][0] = __float_as_uint(As[b][kk + tig][rb + gid]);
                af[mt][1] = __float_as_uint(As[b][kk + tig][rb + gid + 8]);
                af[mt][2] = __float_as_uint(As[b][kk + tig + 4][rb + gid]);
                af[mt][3] = __float_as_uint(As[b][kk + tig + 4][rb + gid + 8]);
            }
            #pragma unroll
            for (int nt = 0; nt < 8; nt++) {
                int cb = nw * 64 + nt * 8;
                uint32_t bf[2];
                bf[0] = __float_as_uint(Bs[b][kk + tig][cb + gid]);
                bf[1] = __float_as_uint(Bs[b][kk + tig + 4][cb + gid]);
                mma8(acc[0][nt], af[0], bf);
                mma8(acc[1][nt], af[1], bf);
            }
        }
        if (n + 1 < NIT) STS(b ^ 1);
        __syncthreads();
    }
    #pragma unroll
    for (int mt = 0; mt < 2; mt++) {
        int r0 = rowBase + mw * 32 + mt * 16 + gid;
        #pragma unroll
        for (int nt = 0; nt < 8; nt++) {
            int c0 = nw * 64 + nt * 8 + tig * 2;
            float b0 = bias[head * FH + c0], b1 = bias[head * FH + c0 + 1];
            float2 lo = {acc[mt][nt][0] + b0, acc[mt][nt][1] + b1};
            float2 hi = {acc[mt][nt][2] + b0, acc[mt][nt][3] + b1};
            *(float2*)(C + (size_t)r0 * FCAT + head * FH + c0) = lo;
            *(float2*)(C + (size_t)(r0 + 8) * FCAT + head * FH + c0) = hi;
        }
    }
}

// ---------------- fused logits + global max + B pairs + bf16 pack ------------
template <int COLS, int NHH>
__global__ __launch_bounds__(256) void sdotpack_k(
    const float* __restrict__ Hmat,
    const float* __restrict__ a1, const float* __restrict__ a2,
    const float* __restrict__ ab,
    float* __restrict__ s1, float2* __restrict__ Bp,
    unsigned* __restrict__ Tenc, uint32_t* __restrict__ Hp)
{
    const int F = COLS / NHH;
    __shared__ float rows[8][COLS];
    __shared__ float sa1[COLS], sa2[COLS];
    const int i0 = blockIdx.x * 8;
    const int t = threadIdx.x;
    for (int c = t; c < COLS; c += 256) { sa1[c] = a1[c]; sa2[c] = a2[c]; }
    for (int idx = t * 4; idx < 8 * COLS; idx += 1024) {
        int r = idx / COLS, c = idx % COLS;
        *(float4*)&rows[r][c] = *(const float4*)(Hmat + (size_t)(i0 + r) * COLS + c);
    }
    __syncthreads();

    const int w = t >> 5, lane = t & 31;
    float d1h[NHH], d2h[NHH];
    #pragma unroll
    for (int h = 0; h < NHH; h++) { d1h[h] = 0.f; d2h[h] = 0.f; }
    #pragma unroll
    for (int q = 0; q < COLS / 32; q++) {
        int c = lane + 32 * q;
        int h = q / (F / 32);
        float v = rows[w][c];
        d1h[h] = fmaf(v, sa1[c], d1h[h]);
        d2h[h] = fmaf(v, sa2[c], d2h[h]);
    }
    #pragma unroll
    for (int h = 0; h < NHH; h++) {
        #pragma unroll
        for (int off = 16; off; off >>= 1) {
            d1h[h] += __shfl_xor_sync(0xffffffffu, d1h[h], off);
            d2h[h] += __shfl_xor_sync(0xffffffffu, d2h[h], off);
        }
    }
    if (lane == 0) {
        int i = i0 + w;
        #pragma unroll
        for (int h = 0; h < NHH; h++) {
            s1[h * NN + i] = d1h[h];
            float tv = d2h[h] + ab[h];
            atomicMax(&Tenc[h], fenc(tv));
            Bp[h * NN + i] = make_float2(__expf(tv), __expf(0.2f * tv));
        }
    }
    for (int idx = t; idx < 4 * COLS; idx += 256) {
        int p = idx / COLS, c = idx % COLS;
        Hp[(size_t)(i0 / 2 + p) * COLS + c] = packbf(rows[2 * p][c], rows[2 * p + 1][c]);
    }
}

// ---------------- stage1 aggregation: bf16 mma, 256 thr, BK=32 ---------------
// BM=64, BN=128, BK=32. grid (NN/64, NH, JS1)
__global__ __launch_bounds__(256) void agg1_k(
    const unsigned* __restrict__ bitsT,
    const float* __restrict__ s1a,
    const float2* __restrict__ Bp,
    const unsigned* __restrict__ Tg,
    const uint32_t* __restrict__ Hp,
    float* __restrict__ part, float* __restrict__ psums)
{
    const int SL = NN / JS1;                       // 1024
    __shared__ __align__(16) uint32_t Ps2[2][16][72];
    __shared__ __align__(16) uint32_t Hs2[2][16][136];
    __shared__ __align__(16) float2 sBp[SL];       // 8 KB
    __shared__ unsigned sbits[64][33];             // 8.4 KB
    __shared__ float spart[4][64];

    const int head = blockIdx.y;
    const int i0 = blockIdx.x * 64;
    const int kb = blockIdx.z;
    const int t = threadIdx.x;
    const int lane = t & 31, wid = t >> 5;
    const int gid = lane >> 2, tig = lane & 3;
    const int mw = wid >> 2, nwq = wid & 3;
    const int r = t & 63, quarter = t >> 6;
    const int js = kb * SL;

    float T = fdec(Tg[head]);
    float s1v = s1a[head * NN + i0 + r];
    float zz = s1v + T;
    float cc = fmaxf(zz, 0.2f * zz);
    float Av  = __expf(s1v - cc);
    float A2v = __expf(0.2f * s1v - cc);

    {
        const float2* BpH = Bp + head * NN + js;
        for (int q = t; q < SL; q += 256) sBp[q] = BpH[q];
        #pragma unroll
        for (int k = 0; k < SL / 32; k += 4) {
            int w = quarter + k;
            sbits[r][w] = bitsT[(size_t)(js / 32 + w) * NN + i0 + r];
        }
    }
    uint32_t hs0 = (uint32_t)__cvta_generic_to_shared(&Hs2[0][0][0]);
    __syncthreads();

    float acc[2][4][4] = {};
    float psum = 0.f;
    const int NCH = SL / 32;                       // 32 chunks

    auto fill = [&](int n, int b) {
        int jl = n * 32;
        unsigned w = sbits[r][n];
        unsigned hw = w >> (quarter * 8);
        const float4* bv = (const float4*)(&sBp[jl + quarter * 8]);
        #pragma unroll
        for (int q = 0; q < 4; q++) {
            float4 f = bv[q];
            float p0 = fmaxf(Av * f.x, A2v * f.y);
            float p1 = fmaxf(Av * f.z, A2v * f.w);
            int m0 = ((int)(hw << (31 - 2 * q))) >> 31;
            int m1 = ((int)(hw << (30 - 2 * q))) >> 31;
            p0 = __uint_as_float(__float_as_uint(p0) & (unsigned)m0);
            p1 = __uint_as_float(__float_as_uint(p1) & (unsigned)m1);
            __nv_bfloat162 pb = __floats2bfloat162_rn(p0, p1);
            psum += __low2float(pb) + __high2float(pb);
            Ps2[b][quarter * 4 + q][r] = *reinterpret_cast<uint32_t*>(&pb);
        }
        const uint32_t* hsrc = Hp + (size_t)((js + jl) >> 1) * FCAT + head * FH;
        uint32_t hb = hs0 + (uint32_t)b * (16 * 136 * 4);
        #pragma unroll
        for (int v = 0; v < 2; v++) {
            int idx = t + v * 256;
            int kr = idx >> 5, c16 = idx & 31;
            cpa16(hb + kr * (136 * 4) + c16 * 16,
                  hsrc + (size_t)kr * FCAT + c16 * 4);
        }
    };

    fill(0, 0);
    CP_COMMIT();
    CP_WAIT0();
    __syncthreads();
    for (int n = 0; n < NCH; n++) {
        const int b = n & 1;
        if (n + 1 < NCH) { fill(n + 1, b ^ 1); CP_COMMIT(); }
        #pragma unroll
        for (int ks = 0; ks < 2; ks++) {
            int kk = ks * 8;
            uint32_t af[2][4];
            #pragma unroll
            for (int mt = 0; mt < 2; mt++) {
                int rb = mw * 32 + mt * 16;
                af[mt][0] = Ps2[b][kk + tig][rb + gid];
                af[mt][1] = Ps2[b][kk + tig][rb + gid + 8];
                af[mt][2] = Ps2[b][kk + tig + 4][rb + gid];
                af[mt][3] = Ps2[b][kk + tig + 4][rb + gid + 8];
            }
            #pragma unroll
            for (int nt = 0; nt < 4; nt++) {
                int cb = nwq * 32 + nt * 8;
                uint32_t bf[2];
                bf[0] = Hs2[b][kk + tig][cb + gid];
                bf[1] = Hs2[b][kk + tig + 4][cb + gid];
                mma16(acc[0][nt], af[0], bf);
                mma16(acc[1][nt], af[1], bf);
            }
        }
        CP_WAIT0();
        __syncthreads();
    }
    spart[quarter][r] = psum;
    __syncthreads();
    if (t < 64)
        psums[((size_t)kb * NH + head) * NN + i0 + t] =
            spart[0][t] + spart[1][t] + spart[2][t] + spart[3][t];
    float* pb = part + (size_t)kb * NN * FCAT;
    #pragma unroll
    for (int mt = 0; mt < 2; mt++) {
        int r0 = i0 + mw * 32 + mt * 16 + gid;
        #pragma unroll
        for (int nt = 0; nt < 4; nt++) {
            int c0 = head * FH + nwq * 32 + nt * 8 + tig * 2;
            float2 lo = {acc[mt][nt][0], acc[mt][nt][1]};
            float2 hi = {acc[mt][nt][2], acc[mt][nt][3]};
            *(float2*)(pb + (size_t)r0 * FCAT + c0) = lo;
            *(float2*)(pb + (size_t)(r0 + 8) * FCAT + c0) = hi;
        }
    }
}

// ---------------- stage1 combine: normalize + elu -> x2 ----------------------
__global__ __launch_bounds__(128) void combine1_k(
    const float* __restrict__ p1, const float* __restrict__ sp1,
    float* __restrict__ x2)
{
    int i = blockIdx.x, t = threadIdx.x;
    int c = t * 4;
    int head = c >> 7;
    float s = 0.f;
    #pragma unroll
    for (int k = 0; k < JS1; k++)
        s += sp1[((size_t)k * NH + head) * NN + i];
    float inv = 1.f / s;
    float4 acc = {0.f, 0.f, 0.f, 0.f};
    #pragma unroll
    for (int k = 0; k < JS1; k++) {
        float4 a = *(const float4*)(p1 + (size_t)k * NN * FCAT + (size_t)i * FCAT + c);
        acc.x += a.x; acc.y += a.y; acc.z += a.z; acc.w += a.w;
    }
    float4 o; float v;
    v = acc.x * inv; o.x = v > 0.f ? v : expm1f(v);
    v = acc.y * inv; o.y = v > 0.f ? v : expm1f(v);
    v = acc.z * inv; o.z = v > 0.f ? v : expm1f(v);
    v = acc.w * inv; o.w = v > 0.f ? v : expm1f(v);
    *(float4*)(x2 + (size_t)i * FCAT + c) = o;
}

// ---------------- stage2 feature GEMM (tf32 mma, reg double buffer) ----------
__global__ __launch_bounds__(128) void gemm2_k(
    const float* __restrict__ A, const float* __restrict__ W,
    const float* __restrict__ bias, float* __restrict__ C)
{
    __shared__ float As[2][16][72];
    __shared__ float Bs[2][16][72];
    const int rowBase = blockIdx.x * 64;
    const int t = threadIdx.x;
    const int lane = t & 31, wid = t >> 5;
    const int gid = lane >> 2, tig = lane & 3;
    const int mw = wid >> 1, nw = wid & 1;
    const int arow = t >> 1, akc = (t & 1) << 3;

    float acc[2][4][4] = {};
    float ar[8], br[8];

    auto LDG = [&](int k0) {
        float4 a0 = *(const float4*)(A + (size_t)(rowBase + arow) * FCAT + k0 + akc);
        float4 a1 = *(const float4*)(A + (size_t)(rowBase + arow) * FCAT + k0 + akc + 4);
        ar[0] = a0.x; ar[1] = a0.y; ar[2] = a0.z; ar[3] = a0.w;
        ar[4] = a1.x; ar[5] = a1.y; ar[6] = a1.z; ar[7] = a1.w;
        #pragma unroll
        for (int v = 0; v < 2; v++) {
            int idx = t + v * 128;
            int kr = idx >> 4, cc = (idx & 15) << 2;
            float4 b = *(const float4*)(W + (size_t)(k0 + kr) * FOUT + cc);
            br[4 * v + 0] = b.x; br[4 * v + 1] = b.y;
            br[4 * v + 2] = b.z; br[4 * v + 3] = b.w;
        }
    };
    auto STS = [&](int bb) {
        #pragma unroll
        for (int q = 0; q < 8; q++) As[bb][akc + q][arow] = tf32r(ar[q]);
        #pragma unroll
        for (int v = 0; v < 2; v++) {
            int idx = t + v * 128;
            int kr = idx >> 4, cc = (idx & 15) << 2;
            float4 o = {tf32r(br[4 * v]), tf32r(br[4 * v + 1]),
                        tf32r(br[4 * v + 2]), tf32r(br[4 * v + 3])};
            *(float4*)&Bs[bb][kr][cc] = o;
        }
    };

    LDG(0); STS(0);
    __syncthreads();
    const int NIT = FCAT / 16;
    for (int n = 0; n < NIT; n++) {
        const int b = n & 1;
        if (n + 1 < NIT) LDG((n + 1) * 16);
        #pragma unroll
        for (int kc = 0; kc < 2; kc++) {
            int kk = kc * 8;
            uint32_t af[2][4];
            #pragma unroll
            for (int mt = 0; mt < 2; mt++) {
                int rb = mw * 32 + mt * 16;
                af[mt][0] = __float_as_uint(As[b][kk + tig][rb + gid]);
                af[mt][1] = __float_as_uint(As[b][kk + tig][rb + gid + 8]);
                af[mt][2] = __float_as_uint(As[b][kk + tig + 4][rb + gid]);
                af[mt][3] = __float_as_uint(As[b][kk + tig + 4][rb + gid + 8]);
            }
            #pragma unroll
            for (int nt = 0; nt < 4; nt++) {
                int cb = nw * 32 + nt * 8;
                uint32_t bf[2];
                bf[0] = __float_as_uint(Bs[b][kk + tig][cb + gid]);
                bf[1] = __float_as_uint(Bs[b][kk + tig + 4][cb + gid]);
                mma8(acc[0][nt], af[0], bf);
                mma8(acc[1][nt], af[1], bf);
            }
        }
        if (n + 1 < NIT) STS(b ^ 1);
        __syncthreads();
    }
    #pragma unroll
    for (int mt = 0; mt < 2; mt++) {
        int r0 = rowBase + mw * 32 + mt * 16 + gid;
        #pragma unroll
        for (int nt = 0; nt < 4; nt++) {
            int c0 = nw * 32 + nt * 8 + tig * 2;
            float b0 = bias[c0], b1 = bias[c0 + 1];
            float2 lo = {acc[mt][nt][0] + b0, acc[mt][nt][1] + b1};
            float2 hi = {acc[mt][nt][2] + b0, acc[mt][nt][3] + b1};
            *(float2*)(C + (size_t)r0 * FOUT + c0) = lo;
            *(float2*)(C + (size_t)(r0 + 8) * FOUT + c0) = hi;
        }
    }
}

// ---------------- stage2 aggregation split-K (bf16 mma, 256 thr, BK=32) -----
// BM=64, BN=64, BK=32. grid (NN/64, JS2)
__global__ __launch_bounds__(256) void agg2_k(
    const unsigned* __restrict__ bitsT,
    const float* __restrict__ s1a,
    const float2* __restrict__ Bp,
    const unsigned* __restrict__ Tg,
    const uint32_t* __restrict__ Hp,
    float* __restrict__ part, float* __restrict__ psums)
{
    const int SL = NN / JS2;                       // 512
    __shared__ __align__(16) uint32_t Ps2[2][16][72];
    __shared__ __align__(16) uint32_t Hs2[2][16][72];
    __shared__ __align__(16) float2 sBp[SL];
    __shared__ unsigned sbits[64][17];
    __shared__ float spart[4][64];

    const int i0 = blockIdx.x * 64;
    const int kb = blockIdx.y;
    const int t = threadIdx.x;
    const int lane = t & 31, wid = t >> 5;
    const int gid = lane >> 2, tig = lane & 3;
    const int mw = wid >> 2, nwq = wid & 3;
    const int r = t & 63, quarter = t >> 6;
    const int js = kb * SL;

    float T = fdec(Tg[0]);
    float s1v = s1a[i0 + r];
    float zz = s1v + T;
    float cc = fmaxf(zz, 0.2f * zz);
    float Av  = __expf(s1v - cc);
    float A2v = __expf(0.2f * s1v - cc);

    {
        const float2* BpS = Bp + js;
        for (int q = t; q < SL; q += 256) sBp[q] = BpS[q];
        #pragma unroll
        for (int k = 0; k < SL / 32; k += 4) {
            int w = quarter + k;
            sbits[r][w] = bitsT[(size_t)(js / 32 + w) * NN + i0 + r];
        }
    }
    uint32_t hs0 = (uint32_t)__cvta_generic_to_shared(&Hs2[0][0][0]);
    __syncthreads();

    float acc[2][2][4] = {};
    float psum = 0.f;
    const int NCH = SL / 32;                       // 16 chunks

    auto fill = [&](int n, int b) {
        int jl = n * 32;
        unsigned w = sbits[r][n];
        unsigned hw = w >> (quarter * 8);
        const float4* bv = (const float4*)(&sBp[jl + quarter * 8]);
        #pragma unroll
        for (int q = 0; q < 4; q++) {
            float4 f = bv[q];
            float p0 = fmaxf(Av * f.x, A2v * f.y);
            float p1 = fmaxf(Av * f.z, A2v * f.w);
            int m0 = ((int)(hw << (31 - 2 * q))) >> 31;
            int m1 = ((int)(hw << (30 - 2 * q))) >> 31;
            p0 = __uint_as_float(__float_as_uint(p0) & (unsigned)m0);
            p1 = __uint_as_float(__float_as_uint(p1) & (unsigned)m1);
            __nv_bfloat162 pb = __floats2bfloat162_rn(p0, p1);
            psum += __low2float(pb) + __high2float(pb);
            Ps2[b][quarter * 4 + q][r] = *reinterpret_cast<uint32_t*>(&pb);
        }
        const uint32_t* hsrc = Hp + (size_t)((js + jl) >> 1) * FOUT;
        uint32_t hb = hs0 + (uint32_t)b * (16 * 72 * 4);
        {
            int kr = t >> 4, c16 = t & 15;
            cpa16(hb + kr * (72 * 4) + c16 * 16,
                  hsrc + (size_t)kr * FOUT + c16 * 4);
        }
    };

    fill(0, 0);
    CP_COMMIT();
    CP_WAIT0();
    __syncthreads();
    for (int n = 0; n < NCH; n++) {
        const int b = n & 1;
        if (n + 1 < NCH) { fill(n + 1, b ^ 1); CP_COMMIT(); }
        #pragma unroll
        for (int ks = 0; ks < 2; ks++) {
            int kk = ks * 8;
            uint32_t af[2][4];
            #pragma unroll
            for (int mt = 0; mt < 2; mt++) {
                int rb = mw * 32 + mt * 16;
                af[mt][0] = Ps2[b][kk + tig][rb + gid];
                af[mt][1] = Ps2[b][kk + tig][rb + gid + 8];
                af[mt][2] = Ps2[b][kk + tig + 4][rb + gid];
                af[mt][3] = Ps2[b][kk + tig + 4][rb + gid + 8];
            }
            #pragma unroll
            for (int nt = 0; nt < 2; nt++) {
                int cb = nwq * 16 + nt * 8;
                uint32_t bf[2];
                bf[0] = Hs2[b][kk + tig][cb + gid];
                bf[1] = Hs2[b][kk + tig + 4][cb + gid];
                mma16(acc[0][nt], af[0], bf);
                mma16(acc[1][nt], af[1], bf);
            }
        }
        CP_WAIT0();
        __syncthreads();
    }
    spart[quarter][r] = psum;
    __syncthreads();
    if (t < 64)
        psums[(size_t)kb * NN + i0 + t] =
            spart[0][t] + spart[1][t] + spart[2][t] + spart[3][t];
    float* pb = part + (size_t)kb * NN * FOUT;
    #pragma unroll
    for (int mt = 0; mt < 2; mt++) {
        int r0 = i0 + mw * 32 + mt * 16 + gid;
        #pragma unroll
        for (int nt = 0; nt < 2; nt++) {
            int c0 = nwq * 16 + nt * 8 + tig * 2;
            float2 lo = {acc[mt][nt][0], acc[mt][nt][1]};
            float2 hi = {acc[mt][nt][2], acc[mt][nt][3]};
            *(float2*)(pb + (size_t)r0 * FOUT + c0) = lo;
            *(float2*)(pb + (size_t)(r0 + 8) * FOUT + c0) = hi;
        }
    }
}

// ---------------- combine partials + normalize + elu + log_softmax ----------
__global__ void combine_k(const float* __restrict__ part,
                          const float* __restrict__ psums,
                          float* __restrict__ out)
{
    int i = blockIdx.x, c = threadIdx.x;  // 64 threads
    float v = 0.f, s = 0.f;
    #pragma unroll
    for (int k = 0; k < JS2; k++) {
        v += part[(size_t)k * NN * FOUT + (size_t)i * FOUT + c];
        s += psums[(size_t)k * NN + i];
    }
    v /= s;
    float e = v > 0.f ? v : expm1f(v);
    __shared__ float sh[4];
    float m = e;
    #pragma unroll
    for (int off = 16; off; off >>= 1)
        m = fmaxf(m, __shfl_xor_sync(0xffffffffu, m, off));
    if ((c & 31) == 0) sh[c >> 5] = m;
    __syncthreads();
    m = fmaxf(sh[0], sh[1]);
    float se = expf(e - m);
    #pragma unroll
    for (int off = 16; off; off >>= 1)
        se += __shfl_xor_sync(0xffffffffu, se, off);
    if ((c & 31) == 0) sh[2 + (c >> 5)] = se;
    __syncthreads();
    se = sh[2] + sh[3];
    out[(size_t)i * FOUT + c] = e - (m + logf(se));
}

// ---------------- launch -----------------------------------------------------
extern "C" void kernel_launch(void* const* d_in, const int* in_sizes, int n_in,
                              void* d_out, int out_size)
{
    const float* X    = (const float*)d_in[0];
    const int*   adj  = (const int*)  d_in[1];
    const float* W_h  = (const float*)d_in[2];
    const float* b_h  = (const float*)d_in[3];
    const float* a1_h = (const float*)d_in[4];
    const float* a2_h = (const float*)d_in[5];
    const float* ab_h = (const float*)d_in[6];
    const float* W_o  = (const float*)d_in[7];
    const float* b_o  = (const float*)d_in[8];
    const float* a1_o = (const float*)d_in[9];
    const float* a2_o = (const float*)d_in[10];
    const float* ab_o = (const float*)d_in[11];
    float* out = (float*)d_out;

    unsigned *bitsT, *Tenc;
    uint32_t *Hp1, *Hp2;
    float *hcat, *x2, *h2, *s1, *s1o, *p1, *sp1, *p2, *sp2;
    float2 *Bp1, *Bp2;
    cudaGetSymbolAddress((void**)&bitsT, g_bitsT);
    cudaGetSymbolAddress((void**)&Tenc,  g_Tenc);
    cudaGetSymbolAddress((void**)&hcat,  g_hcat);
    cudaGetSymbolAddress((void**)&x2,    g_x2);
    cudaGetSymbolAddress((void**)&h2,    g_h2);
    cudaGetSymbolAddress((void**)&Hp1,   g_Hp1);
    cudaGetSymbolAddress((void**)&Hp2,   g_Hp2);
    cudaGetSymbolAddress((void**)&s1,    g_s1);
    cudaGetSymbolAddress((void**)&s1o,   g_s1o);
    cudaGetSymbolAddress((void**)&Bp1,   g_Bp1);
    cudaGetSymbolAddress((void**)&Bp2,   g_Bp2);
    cudaGetSymbolAddress((void**)&p1,    g_p1);
    cudaGetSymbolAddress((void**)&sp1,   g_sp1);
    cudaGetSymbolAddress((void**)&p2,    g_p2);
    cudaGetSymbolAddress((void**)&sp2,   g_sp2);

    pack_k<<<NN, 256>>>(adj, bitsT, Tenc);

    {   dim3 grid(NN / 64, NH);
        gemm1_k<<<grid, 128>>>(X, W_h, b_h, hcat); }

    sdotpack_k<FCAT, NH><<<NN / 8, 256>>>(hcat, a1_h, a2_h, ab_h,
                                          s1, Bp1, Tenc, Hp1);

    {   dim3 grid(NN / 64, NH, JS1);
        agg1_k<<<grid, 256>>>(bitsT, s1, Bp1, Tenc, Hp1, p1, sp1); }

    combine1_k<<<NN, 128>>>(p1, sp1, x2);

    gemm2_k<<<NN / 64, 128>>>(x2, W_o, b_o, h2);

    sdotpack_k<FOUT, 1><<<NN / 8, 256>>>(h2, a1_o, a2_o, ab_o,
                                         s1o, Bp2, Tenc + NH, Hp2);

    {   dim3 grid(NN / 64, JS2);
        agg2_k<<<grid, 256>>>(bitsT, s1o, Bp2, Tenc + NH, Hp2, p2, sp2); }

    combine_k<<<NN, 64>>>(p2, sp2, out);
}